// round 2
// baseline (speedup 1.0000x reference)
#include <cuda_runtime.h>
#include <cuda_bf16.h>
#include <cstdint>

// Problem constants
#define BB 4
#define NN 2048
#define KC 2048
#define DD 1024
#define HH 16
#define HD 64
#define ATTN_SCALE 0.125f
#define RMS_EPS 1e-6f

// ---------------------------------------------------------------------------
// Scratch (device globals — no allocations allowed)
// ---------------------------------------------------------------------------
__device__ float g_ctxn[BB * KC * DD];      // rms-normed ctx        32 MB
__device__ float g_q[BB * NN * DD];         // q projection          32 MB
__device__ float g_kv[BB * KC * 2 * DD];    // kv projection         64 MB
__device__ float g_attn[BB * NN * DD];      // attention output      32 MB

// ---------------------------------------------------------------------------
// RMSNorm: one block per row of 1024 floats (B*KC = 8192 rows)
// ---------------------------------------------------------------------------
__global__ __launch_bounds__(256) void rmsnorm_kernel(const float* __restrict__ ctx)
{
    const int row = blockIdx.x;
    const float4* p = reinterpret_cast<const float4*>(ctx + (size_t)row * DD);
    float4 v = p[threadIdx.x];
    float s = v.x * v.x + v.y * v.y + v.z * v.z + v.w * v.w;

    // warp reduce
    #pragma unroll
    for (int o = 16; o > 0; o >>= 1) s += __shfl_xor_sync(0xffffffffu, s, o);

    __shared__ float ws[8];
    if ((threadIdx.x & 31) == 0) ws[threadIdx.x >> 5] = s;
    __syncthreads();
    float tot = 0.f;
    #pragma unroll
    for (int i = 0; i < 8; i++) tot += ws[i];

    const float r = rsqrtf(tot * (1.0f / (float)DD) + RMS_EPS);
    float4 o4 = make_float4(v.x * r, v.y * r, v.z * r, v.w * r);
    reinterpret_cast<float4*>(g_ctxn + (size_t)row * DD)[threadIdx.x] = o4;
}

// ---------------------------------------------------------------------------
// Classic 128x128x8 SGEMM with bias: C[M,N] = A[M,K] @ W[K,N] + bias[N]
// 256 threads, 8x8 per-thread microtile. All dims divisible by tiles.
// ---------------------------------------------------------------------------
#define BM 128
#define BN 128
#define BK 8

__global__ __launch_bounds__(256) void sgemm_bias(const float* __restrict__ A,
                                                  const float* __restrict__ W,
                                                  const float* __restrict__ bias,
                                                  float* __restrict__ C,
                                                  int M, int N, int K)
{
    __shared__ float As[BK][BM + 4];   // transposed A tile, padded
    __shared__ float Bs[BK][BN];

    const int tid = threadIdx.x;
    const int tx = tid & 15;
    const int ty = tid >> 4;
    const int row0 = blockIdx.y * BM + ty * 8;
    const int col0 = blockIdx.x * BN + tx * 8;

    // A loader: thread -> (row = tid/2, 4 cols at (tid&1)*4)
    const int arow = tid >> 1;
    const int acol = (tid & 1) * 4;
    const float* Aptr = A + (size_t)(blockIdx.y * BM + arow) * K + acol;

    // W loader: thread -> (row = tid/32, 4 cols at (tid&31)*4)
    const int brow = tid >> 5;
    const int bcol = (tid & 31) * 4;
    const float* Wptr = W + (size_t)brow * N + blockIdx.x * BN + bcol;

    float acc[8][8];
    #pragma unroll
    for (int i = 0; i < 8; i++)
        #pragma unroll
        for (int j = 0; j < 8; j++) acc[i][j] = 0.f;

    for (int k0 = 0; k0 < K; k0 += BK) {
        float4 av = *reinterpret_cast<const float4*>(Aptr + k0);
        float4 bv = *reinterpret_cast<const float4*>(Wptr + (size_t)k0 * N);
        __syncthreads();
        As[acol + 0][arow] = av.x;
        As[acol + 1][arow] = av.y;
        As[acol + 2][arow] = av.z;
        As[acol + 3][arow] = av.w;
        *reinterpret_cast<float4*>(&Bs[brow][bcol]) = bv;
        __syncthreads();

        #pragma unroll
        for (int k = 0; k < BK; k++) {
            float af[8], bf[8];
            #pragma unroll
            for (int i = 0; i < 8; i++) af[i] = As[k][ty * 8 + i];
            #pragma unroll
            for (int j = 0; j < 8; j++) bf[j] = Bs[k][tx * 8 + j];
            #pragma unroll
            for (int i = 0; i < 8; i++)
                #pragma unroll
                for (int j = 0; j < 8; j++)
                    acc[i][j] = fmaf(af[i], bf[j], acc[i][j]);
        }
    }

    float4 bi0 = *reinterpret_cast<const float4*>(bias + col0);
    float4 bi1 = *reinterpret_cast<const float4*>(bias + col0 + 4);
    #pragma unroll
    for (int i = 0; i < 8; i++) {
        float4 v0 = make_float4(acc[i][0] + bi0.x, acc[i][1] + bi0.y,
                                acc[i][2] + bi0.z, acc[i][3] + bi0.w);
        float4 v1 = make_float4(acc[i][4] + bi1.x, acc[i][5] + bi1.y,
                                acc[i][6] + bi1.z, acc[i][7] + bi1.w);
        float* crow = C + (size_t)(row0 + i) * N + col0;
        *reinterpret_cast<float4*>(crow) = v0;
        *reinterpret_cast<float4*>(crow + 4) = v1;
    }
}

// ---------------------------------------------------------------------------
// Attention: one block per (b, h, n-tile of 64). 256 threads (16x16),
// each thread owns a 4x4 microtile. Clip(-10,10) before exp removes the need
// for online max tracking: accumulate unnormalized O and a running denominator,
// divide at the end.
// smem (dynamic): Qs[64][65] + KPs[64][65] (K tile, reused for P) +
//                 Vs[64][65] + dsum[64]  = 50176 bytes
// ---------------------------------------------------------------------------
#define AP 65  // smem row pitch
#define ATTN_SMEM ((3 * 64 * AP + 64) * (int)sizeof(float))

__global__ __launch_bounds__(256) void attn_kernel()
{
    extern __shared__ float sm[];
    float* Qs   = sm;
    float* KPs  = sm + 64 * AP;
    float* Vs   = sm + 2 * 64 * AP;
    float* dsum = sm + 3 * 64 * AP;

    const int tid = threadIdx.x;
    const int tx = tid & 15;
    const int ty = tid >> 4;
    const int bh = blockIdx.x;
    const int b = bh >> 4;
    const int h = bh & 15;
    const int n0 = blockIdx.y * 64;

    // Load Q tile (pre-scaled)
    for (int s = tid; s < 64 * 64; s += 256) {
        int r = s >> 6, c = s & 63;
        Qs[r * AP + c] =
            g_q[((size_t)(b * NN + n0 + r)) * DD + h * HD + c] * ATTN_SCALE;
    }
    if (tid < 64) dsum[tid] = 0.f;

    const int ri = ty * 4;
    const int cj = tx * 4;
    float o[4][4];
    #pragma unroll
    for (int i = 0; i < 4; i++)
        #pragma unroll
        for (int j = 0; j < 4; j++) o[i][j] = 0.f;

    for (int k0 = 0; k0 < KC; k0 += 64) {
        __syncthreads();  // prior-iter reads of KPs/Vs done (and Q visible on iter 0)

        // Load K and V tiles
        for (int s = tid; s < 64 * 64; s += 256) {
            int r = s >> 6, c = s & 63;
            size_t base = ((size_t)(b * KC + k0 + r)) * (2 * DD) + h * HD + c;
            KPs[r * AP + c] = g_kv[base];
            Vs[r * AP + c]  = g_kv[base + DD];
        }
        __syncthreads();

        // S = Q @ K^T  (4x4 per thread)
        float acc[4][4];
        #pragma unroll
        for (int i = 0; i < 4; i++)
            #pragma unroll
            for (int j = 0; j < 4; j++) acc[i][j] = 0.f;

        #pragma unroll 8
        for (int d = 0; d < 64; ++d) {
            float qf[4], kf[4];
            #pragma unroll
            for (int i = 0; i < 4; i++) qf[i] = Qs[(ri + i) * AP + d];
            #pragma unroll
            for (int j = 0; j < 4; j++) kf[j] = KPs[(cj + j) * AP + d];
            #pragma unroll
            for (int i = 0; i < 4; i++)
                #pragma unroll
                for (int j = 0; j < 4; j++)
                    acc[i][j] = fmaf(qf[i], kf[j], acc[i][j]);
        }
        __syncthreads();  // everyone done reading K before overwrite with P

        // P = exp(clip(S))  -> overwrite K tile
        #pragma unroll
        for (int i = 0; i < 4; i++)
            #pragma unroll
            for (int j = 0; j < 4; j++)
                KPs[(ri + i) * AP + (cj + j)] =
                    __expf(fminf(fmaxf(acc[i][j], -10.f), 10.f));
        __syncthreads();

        // running denominator (threads 0..63 each own one row)
        if (tid < 64) {
            float s = 0.f;
            #pragma unroll 8
            for (int t = 0; t < 64; t++) s += KPs[tid * AP + t];
            dsum[tid] += s;
        }

        // O += P @ V
        #pragma unroll 8
        for (int t = 0; t < 64; t++) {
            float pf[4], vf[4];
            #pragma unroll
            for (int i = 0; i < 4; i++) pf[i] = KPs[(ri + i) * AP + t];
            #pragma unroll
            for (int j = 0; j < 4; j++) vf[j] = Vs[t * AP + cj + j];
            #pragma unroll
            for (int i = 0; i < 4; i++)
                #pragma unroll
                for (int j = 0; j < 4; j++)
                    o[i][j] = fmaf(pf[i], vf[j], o[i][j]);
        }
    }
    __syncthreads();  // dsum final

    #pragma unroll
    for (int i = 0; i < 4; i++) {
        const float inv = 1.0f / dsum[ri + i];
        #pragma unroll
        for (int j = 0; j < 4; j++)
            g_attn[((size_t)(b * NN + n0 + ri + i)) * DD + h * HD + cj + j] =
                o[i][j] * inv;
    }
}

// ---------------------------------------------------------------------------
// attn.mean(): each softmax row sums to exactly 1 -> mean == 1/KC.
// ---------------------------------------------------------------------------
__global__ void finalize_mean(float* out, int out_size)
{
    const int base = BB * NN * DD;
    for (int i = base + threadIdx.x; i < out_size; i += blockDim.x)
        out[i] = 1.0f / (float)KC;
}

// ---------------------------------------------------------------------------
// Launch
// ---------------------------------------------------------------------------
extern "C" void kernel_launch(void* const* d_in, const int* in_sizes, int n_in,
                              void* d_out, int out_size)
{
    const float* x      = (const float*)d_in[0];
    const float* ctx    = (const float*)d_in[1];
    const float* q_w    = (const float*)d_in[2];
    const float* q_b    = (const float*)d_in[3];
    const float* kv_w   = (const float*)d_in[4];
    const float* kv_b   = (const float*)d_in[5];
    const float* proj_w = (const float*)d_in[6];
    const float* proj_b = (const float*)d_in[7];
    float* out = (float*)d_out;

    float *ctxn_p, *q_p, *kv_p, *attn_p;
    cudaGetSymbolAddress((void**)&ctxn_p, g_ctxn);
    cudaGetSymbolAddress((void**)&q_p, g_q);
    cudaGetSymbolAddress((void**)&kv_p, g_kv);
    cudaGetSymbolAddress((void**)&attn_p, g_attn);

    cudaFuncSetAttribute(attn_kernel,
                         cudaFuncAttributeMaxDynamicSharedMemorySize, ATTN_SMEM);

    // 1. ctxn = rms_norm(ctx)
    rmsnorm_kernel<<<BB * KC, 256>>>(ctx);

    // 2. q = x @ q_w + q_b            [8192,1024] x [1024,1024]
    sgemm_bias<<<dim3(DD / BN, BB * NN / BM), 256>>>(x, q_w, q_b, q_p,
                                                     BB * NN, DD, DD);

    // 3. kv = ctxn @ kv_w + kv_b      [8192,1024] x [1024,2048]
    sgemm_bias<<<dim3(2 * DD / BN, BB * KC / BM), 256>>>(ctxn_p, kv_w, kv_b, kv_p,
                                                         BB * KC, 2 * DD, DD);

    // 4. attention
    attn_kernel<<<dim3(BB * HH, NN / 64), 256, ATTN_SMEM>>>();

    // 5. out = attn_out @ proj_w + proj_b
    sgemm_bias<<<dim3(DD / BN, BB * NN / BM), 256>>>(attn_p, proj_w, proj_b, out,
                                                     BB * NN, DD, DD);

    // 6. attn.mean() == 1/KC exactly
    if (out_size > BB * NN * DD)
        finalize_mean<<<1, 32>>>(out, out_size);
}

// round 3
// speedup vs baseline: 2.6641x; 2.6641x over previous
#include <cuda_runtime.h>
#include <cuda_bf16.h>
#include <cstdint>

#define BB 4
#define NN 2048
#define KC 2048
#define DD 1024
#define HH 16
#define HD 64
#define RMS_EPS 1e-6f

// ---------------------------------------------------------------------------
// Scratch (bf16 hi/lo split arrays)
// ---------------------------------------------------------------------------
__device__ __nv_bfloat16 g_x_hi[BB*NN*DD],   g_x_lo[BB*NN*DD];
__device__ __nv_bfloat16 g_qw_hi[DD*DD],     g_qw_lo[DD*DD];
__device__ __nv_bfloat16 g_kvw_hi[DD*2*DD],  g_kvw_lo[DD*2*DD];
__device__ __nv_bfloat16 g_pw_hi[DD*DD],     g_pw_lo[DD*DD];
__device__ __nv_bfloat16 g_cn_hi[BB*KC*DD],  g_cn_lo[BB*KC*DD];
__device__ __nv_bfloat16 g_q_hi[BB*NN*DD],   g_q_lo[BB*NN*DD];      // pre-scaled by 0.125
__device__ __nv_bfloat16 g_kv_hi[BB*KC*2*DD],g_kv_lo[BB*KC*2*DD];
__device__ __nv_bfloat16 g_ao_hi[BB*NN*DD],  g_ao_lo[BB*NN*DD];

// ---------------------------------------------------------------------------
// PTX helpers
// ---------------------------------------------------------------------------
__device__ __forceinline__ uint32_t smem_u32(const void* p) {
    return (uint32_t)__cvta_generic_to_shared(p);
}
__device__ __forceinline__ void ldsm4(uint32_t a, uint32_t& r0, uint32_t& r1,
                                      uint32_t& r2, uint32_t& r3) {
    asm volatile("ldmatrix.sync.aligned.m8n8.x4.shared.b16 {%0,%1,%2,%3}, [%4];"
                 : "=r"(r0), "=r"(r1), "=r"(r2), "=r"(r3) : "r"(a));
}
__device__ __forceinline__ void ldsm4t(uint32_t a, uint32_t& r0, uint32_t& r1,
                                       uint32_t& r2, uint32_t& r3) {
    asm volatile("ldmatrix.sync.aligned.m8n8.x4.trans.shared.b16 {%0,%1,%2,%3}, [%4];"
                 : "=r"(r0), "=r"(r1), "=r"(r2), "=r"(r3) : "r"(a));
}
__device__ __forceinline__ void mma_bf16(float* c, const uint32_t* a, const uint32_t* b) {
    asm volatile(
        "mma.sync.aligned.m16n8k16.row.col.f32.bf16.bf16.f32 "
        "{%0,%1,%2,%3},{%4,%5,%6,%7},{%8,%9},{%0,%1,%2,%3};\n"
        : "+f"(c[0]), "+f"(c[1]), "+f"(c[2]), "+f"(c[3])
        : "r"(a[0]), "r"(a[1]), "r"(a[2]), "r"(a[3]), "r"(b[0]), "r"(b[1]));
}
__device__ __forceinline__ void cpa16(void* dst, const void* src) {
    uint32_t d = smem_u32(dst);
    asm volatile("cp.async.cg.shared.global [%0], [%1], 16;\n" :: "r"(d), "l"(src));
}
__device__ __forceinline__ void split2(float v, __nv_bfloat16& h, __nv_bfloat16& l) {
    h = __float2bfloat16(v);
    l = __float2bfloat16(v - __bfloat162float(h));
}

// ---------------------------------------------------------------------------
// fp32 -> bf16 hi/lo split
// ---------------------------------------------------------------------------
__global__ __launch_bounds__(256) void split_kernel(const float* __restrict__ src,
                                                    __nv_bfloat16* __restrict__ hi,
                                                    __nv_bfloat16* __restrict__ lo, int n)
{
    int i = (blockIdx.x * 256 + threadIdx.x) * 4;
    if (i >= n) return;
    float4 v = *reinterpret_cast<const float4*>(src + i);
    __nv_bfloat16 h0, l0, h1, l1, h2, l2, h3, l3;
    split2(v.x, h0, l0); split2(v.y, h1, l1);
    split2(v.z, h2, l2); split2(v.w, h3, l3);
    hi[i] = h0; hi[i+1] = h1; hi[i+2] = h2; hi[i+3] = h3;
    lo[i] = l0; lo[i+1] = l1; lo[i+2] = l2; lo[i+3] = l3;
}

// ---------------------------------------------------------------------------
// RMSNorm -> bf16 hi/lo
// ---------------------------------------------------------------------------
__global__ __launch_bounds__(256) void rmsnorm_split(const float* __restrict__ ctx)
{
    const int row = blockIdx.x;
    float4 v = reinterpret_cast<const float4*>(ctx + (size_t)row * DD)[threadIdx.x];
    float s = v.x*v.x + v.y*v.y + v.z*v.z + v.w*v.w;
    #pragma unroll
    for (int o = 16; o > 0; o >>= 1) s += __shfl_xor_sync(0xffffffffu, s, o);
    __shared__ float ws[8];
    if ((threadIdx.x & 31) == 0) ws[threadIdx.x >> 5] = s;
    __syncthreads();
    float tot = 0.f;
    #pragma unroll
    for (int i = 0; i < 8; i++) tot += ws[i];
    const float r = rsqrtf(tot * (1.0f / (float)DD) + RMS_EPS);
    const size_t base = (size_t)row * DD + threadIdx.x * 4;
    __nv_bfloat16 h, l;
    split2(v.x * r, h, l); g_cn_hi[base+0] = h; g_cn_lo[base+0] = l;
    split2(v.y * r, h, l); g_cn_hi[base+1] = h; g_cn_lo[base+1] = l;
    split2(v.z * r, h, l); g_cn_hi[base+2] = h; g_cn_lo[base+2] = l;
    split2(v.w * r, h, l); g_cn_hi[base+3] = h; g_cn_lo[base+3] = l;
}

// ---------------------------------------------------------------------------
// Split-bf16 GEMM: C = (Ahi+Alo)@(Whi+Wlo) + bias, tile 128x128x32,
// 256 threads (8 warps as 4x2), double-buffered cp.async.
// ---------------------------------------------------------------------------
#define GBM 128
#define GBN 128
#define GBK 32
#define APAD 40
#define WPAD 136
#define A_EL (GBM*APAD)
#define W_EL (GBK*WPAD)
#define STG_EL (2*A_EL + 2*W_EL)
#define GEMM_SMEM (2*STG_EL*2)

template<bool SPLIT>
__global__ __launch_bounds__(256, 1) void mmgemm(
    const __nv_bfloat16* __restrict__ Ahi, const __nv_bfloat16* __restrict__ Alo,
    const __nv_bfloat16* __restrict__ Whi, const __nv_bfloat16* __restrict__ Wlo,
    const float* __restrict__ bias, float scale,
    float* __restrict__ Cf, __nv_bfloat16* __restrict__ Chi, __nv_bfloat16* __restrict__ Clo,
    int M, int N, int K)
{
    extern __shared__ __nv_bfloat16 sm[];
    const int tid = threadIdx.x;
    const int wid = tid >> 5, lane = tid & 31;
    const int rowBase = blockIdx.y * GBM;
    const int colBase = blockIdx.x * GBN;
    const int wm = wid & 3;     // 32-row slab
    const int wn = wid >> 2;    // 64-col slab

    auto loadStage = [&](int kc, int s) {
        const int k0 = kc * GBK;
        __nv_bfloat16* Ah = sm + s * STG_EL;
        __nv_bfloat16* Al = Ah + A_EL;
        __nv_bfloat16* Wh = Al + A_EL;
        __nv_bfloat16* Wl = Wh + W_EL;
        #pragma unroll
        for (int i = 0; i < 2; i++) {
            int t = tid + i * 256;
            int r = t >> 2, ch = t & 3;
            size_t ga = (size_t)(rowBase + r) * K + k0 + ch * 8;
            cpa16(Ah + r * APAD + ch * 8, Ahi + ga);
            cpa16(Al + r * APAD + ch * 8, Alo + ga);
            int rw = t >> 4, cw = t & 15;
            size_t gw = (size_t)(k0 + rw) * N + colBase + cw * 8;
            cpa16(Wh + rw * WPAD + cw * 8, Whi + gw);
            cpa16(Wl + rw * WPAD + cw * 8, Wlo + gw);
        }
        asm volatile("cp.async.commit_group;\n");
    };

    float acc[2][8][4];
    #pragma unroll
    for (int mt = 0; mt < 2; mt++)
        #pragma unroll
        for (int nt = 0; nt < 8; nt++)
            #pragma unroll
            for (int e = 0; e < 4; e++) acc[mt][nt][e] = 0.f;

    const int NK = K / GBK;
    loadStage(0, 0);
    for (int kc = 0; kc < NK; kc++) {
        if (kc + 1 < NK) {
            loadStage(kc + 1, (kc + 1) & 1);
            asm volatile("cp.async.wait_group 1;\n");
        } else {
            asm volatile("cp.async.wait_group 0;\n");
        }
        __syncthreads();

        __nv_bfloat16* Ah = sm + (kc & 1) * STG_EL;
        __nv_bfloat16* Al = Ah + A_EL;
        __nv_bfloat16* Wh = Al + A_EL;
        __nv_bfloat16* Wl = Wh + W_EL;

        #pragma unroll
        for (int k16 = 0; k16 < 2; k16++) {
            const int kk = k16 * 16;
            uint32_t ah[2][4], al[2][4];
            #pragma unroll
            for (int mt = 0; mt < 2; mt++) {
                int r = wm * 32 + mt * 16 + (lane & 7) + ((lane >> 3) & 1) * 8;
                int c = kk + (lane >> 4) * 8;
                ldsm4(smem_u32(Ah + r * APAD + c), ah[mt][0], ah[mt][1], ah[mt][2], ah[mt][3]);
                ldsm4(smem_u32(Al + r * APAD + c), al[mt][0], al[mt][1], al[mt][2], al[mt][3]);
            }
            uint32_t bh[8][2], bl[8][2];
            #pragma unroll
            for (int np = 0; np < 4; np++) {
                int r = kk + (lane & 7) + ((lane >> 3) & 1) * 8;
                int c = wn * 64 + np * 16 + (lane >> 4) * 8;
                uint32_t r0, r1, r2, r3;
                ldsm4t(smem_u32(Wh + r * WPAD + c), r0, r1, r2, r3);
                bh[2*np][0] = r0; bh[2*np][1] = r1; bh[2*np+1][0] = r2; bh[2*np+1][1] = r3;
                ldsm4t(smem_u32(Wl + r * WPAD + c), r0, r1, r2, r3);
                bl[2*np][0] = r0; bl[2*np][1] = r1; bl[2*np+1][0] = r2; bl[2*np+1][1] = r3;
            }
            #pragma unroll
            for (int mt = 0; mt < 2; mt++)
                #pragma unroll
                for (int nt = 0; nt < 8; nt++) {
                    mma_bf16(acc[mt][nt], ah[mt], bh[nt]);
                    mma_bf16(acc[mt][nt], ah[mt], bl[nt]);
                    mma_bf16(acc[mt][nt], al[mt], bh[nt]);
                }
        }
        __syncthreads();
    }

    // epilogue
    #pragma unroll
    for (int mt = 0; mt < 2; mt++)
        #pragma unroll
        for (int nt = 0; nt < 8; nt++) {
            int row = rowBase + wm * 32 + mt * 16 + (lane >> 2);
            int col = colBase + wn * 64 + nt * 8 + 2 * (lane & 3);
            float b0 = bias[col], b1 = bias[col + 1];
            float v00 = (acc[mt][nt][0] + b0) * scale;
            float v01 = (acc[mt][nt][1] + b1) * scale;
            float v10 = (acc[mt][nt][2] + b0) * scale;
            float v11 = (acc[mt][nt][3] + b1) * scale;
            if (SPLIT) {
                __nv_bfloat16 h, l;
                size_t i0 = (size_t)row * N + col;
                size_t i1 = (size_t)(row + 8) * N + col;
                split2(v00, h, l); Chi[i0]     = h; Clo[i0]     = l;
                split2(v01, h, l); Chi[i0 + 1] = h; Clo[i0 + 1] = l;
                split2(v10, h, l); Chi[i1]     = h; Clo[i1]     = l;
                split2(v11, h, l); Chi[i1 + 1] = h; Clo[i1 + 1] = l;
            } else {
                size_t i0 = (size_t)row * N + col;
                size_t i1 = (size_t)(row + 8) * N + col;
                Cf[i0] = v00; Cf[i0 + 1] = v01;
                Cf[i1] = v10; Cf[i1 + 1] = v11;
            }
        }
}

// ---------------------------------------------------------------------------
// Attention with split-bf16 mma. Block = (b,h, 128 q-rows); 8 warps, each owns
// 16 q-rows x full 64 cols. kc tiles of 64.
// ---------------------------------------------------------------------------
#define ANT 128
#define AKT 64
#define APITCH 72
#define ATTN_SMEM ((2*ANT*APITCH + 4*AKT*APITCH + 2*ANT*APITCH) * 2 + ANT * 4)

__global__ __launch_bounds__(256, 1) void attn_mma()
{
    extern __shared__ __nv_bfloat16 sm[];
    __nv_bfloat16* Qh = sm;
    __nv_bfloat16* Ql = Qh + ANT * APITCH;
    __nv_bfloat16* Kh = Ql + ANT * APITCH;
    __nv_bfloat16* Kl = Kh + AKT * APITCH;
    __nv_bfloat16* Vh = Kl + AKT * APITCH;
    __nv_bfloat16* Vl = Vh + AKT * APITCH;
    __nv_bfloat16* Ph = Vl + AKT * APITCH;
    __nv_bfloat16* Pl = Ph + ANT * APITCH;
    float* dsum = (float*)(Pl + ANT * APITCH);

    const int tid = threadIdx.x, wid = tid >> 5, lane = tid & 31;
    const int b = blockIdx.x >> 4, h = blockIdx.x & 15;
    const int n0 = blockIdx.y * ANT;

    // Q tile (pre-scaled at q-GEMM epilogue)
    #pragma unroll
    for (int i = 0; i < 4; i++) {
        int t = tid + i * 256;
        int r = t >> 3, ch = t & 7;
        size_t g = (size_t)(b * NN + n0 + r) * DD + h * HD + ch * 8;
        *reinterpret_cast<uint4*>(Qh + r * APITCH + ch * 8) =
            *reinterpret_cast<const uint4*>(g_q_hi + g);
        *reinterpret_cast<uint4*>(Ql + r * APITCH + ch * 8) =
            *reinterpret_cast<const uint4*>(g_q_lo + g);
    }
    if (tid < ANT) dsum[tid] = 0.f;

    float oacc[8][4];
    #pragma unroll
    for (int nt = 0; nt < 8; nt++)
        #pragma unroll
        for (int e = 0; e < 4; e++) oacc[nt][e] = 0.f;

    for (int kc0 = 0; kc0 < KC; kc0 += AKT) {
        __syncthreads();   // prev-iter V reads done; Q/dsum visible on iter 0
        #pragma unroll
        for (int i = 0; i < 2; i++) {
            int t = tid + i * 256;
            int r = t >> 3, ch = t & 7;
            size_t gk = (size_t)(b * KC + kc0 + r) * (2 * DD) + h * HD + ch * 8;
            *reinterpret_cast<uint4*>(Kh + r * APITCH + ch * 8) =
                *reinterpret_cast<const uint4*>(g_kv_hi + gk);
            *reinterpret_cast<uint4*>(Kl + r * APITCH + ch * 8) =
                *reinterpret_cast<const uint4*>(g_kv_lo + gk);
            *reinterpret_cast<uint4*>(Vh + r * APITCH + ch * 8) =
                *reinterpret_cast<const uint4*>(g_kv_hi + gk + DD);
            *reinterpret_cast<uint4*>(Vl + r * APITCH + ch * 8) =
                *reinterpret_cast<const uint4*>(g_kv_lo + gk + DD);
        }
        __syncthreads();

        // S = Q @ K^T
        float sacc[8][4];
        #pragma unroll
        for (int nt = 0; nt < 8; nt++)
            #pragma unroll
            for (int e = 0; e < 4; e++) sacc[nt][e] = 0.f;

        #pragma unroll
        for (int d16 = 0; d16 < 4; d16++) {
            const int dd0 = d16 * 16;
            uint32_t ah[4], al[4];
            {
                int r = wid * 16 + (lane & 7) + ((lane >> 3) & 1) * 8;
                int c = dd0 + (lane >> 4) * 8;
                ldsm4(smem_u32(Qh + r * APITCH + c), ah[0], ah[1], ah[2], ah[3]);
                ldsm4(smem_u32(Ql + r * APITCH + c), al[0], al[1], al[2], al[3]);
            }
            uint32_t bh[8][2], bl[8][2];
            #pragma unroll
            for (int np = 0; np < 4; np++) {
                int r = np * 16 + (lane & 7) + ((lane >> 4)) * 8;   // kc rows
                int c = dd0 + ((lane >> 3) & 1) * 8;                // d
                uint32_t r0, r1, r2, r3;
                ldsm4(smem_u32(Kh + r * APITCH + c), r0, r1, r2, r3);
                bh[2*np][0] = r0; bh[2*np][1] = r1; bh[2*np+1][0] = r2; bh[2*np+1][1] = r3;
                ldsm4(smem_u32(Kl + r * APITCH + c), r0, r1, r2, r3);
                bl[2*np][0] = r0; bl[2*np][1] = r1; bl[2*np+1][0] = r2; bl[2*np+1][1] = r3;
            }
            #pragma unroll
            for (int nt = 0; nt < 8; nt++) {
                mma_bf16(sacc[nt], ah, bh[nt]);
                mma_bf16(sacc[nt], ah, bl[nt]);
                mma_bf16(sacc[nt], al, bh[nt]);
            }
        }

        // P = exp(clip(S)) -> smem (split) + row sums
        float s0 = 0.f, s1 = 0.f;
        const int prow = wid * 16 + (lane >> 2);
        const int pcol0 = 2 * (lane & 3);
        #pragma unroll
        for (int nt = 0; nt < 8; nt++) {
            #pragma unroll
            for (int e = 0; e < 4; e++) {
                float v = __expf(fminf(fmaxf(sacc[nt][e], -10.f), 10.f));
                __nv_bfloat16 hb, lb;
                split2(v, hb, lb);
                int r = prow + ((e >> 1) ? 8 : 0);
                int c = nt * 8 + pcol0 + (e & 1);
                Ph[r * APITCH + c] = hb;
                Pl[r * APITCH + c] = lb;
                if (e >> 1) s1 += v; else s0 += v;
            }
        }
        s0 += __shfl_xor_sync(0xffffffffu, s0, 1);
        s0 += __shfl_xor_sync(0xffffffffu, s0, 2);
        s1 += __shfl_xor_sync(0xffffffffu, s1, 1);
        s1 += __shfl_xor_sync(0xffffffffu, s1, 2);
        if ((lane & 3) == 0) { dsum[prow] += s0; dsum[prow + 8] += s1; }
        __syncthreads();

        // O += P @ V
        #pragma unroll
        for (int k16 = 0; k16 < 4; k16++) {
            const int kk = k16 * 16;
            uint32_t ah[4], al[4];
            {
                int r = wid * 16 + (lane & 7) + ((lane >> 3) & 1) * 8;
                int c = kk + (lane >> 4) * 8;
                ldsm4(smem_u32(Ph + r * APITCH + c), ah[0], ah[1], ah[2], ah[3]);
                ldsm4(smem_u32(Pl + r * APITCH + c), al[0], al[1], al[2], al[3]);
            }
            uint32_t bh[8][2], bl[8][2];
            #pragma unroll
            for (int np = 0; np < 4; np++) {
                int rv = kk + (lane & 7) + ((lane >> 3) & 1) * 8;   // kc rows
                int cv = np * 16 + (lane >> 4) * 8;                 // d
                uint32_t r0, r1, r2, r3;
                ldsm4t(smem_u32(Vh + rv * APITCH + cv), r0, r1, r2, r3);
                bh[2*np][0] = r0; bh[2*np][1] = r1; bh[2*np+1][0] = r2; bh[2*np+1][1] = r3;
                ldsm4t(smem_u32(Vl + rv * APITCH + cv), r0, r1, r2, r3);
                bl[2*np][0] = r0; bl[2*np][1] = r1; bl[2*np+1][0] = r2; bl[2*np+1][1] = r3;
            }
            #pragma unroll
            for (int nt = 0; nt < 8; nt++) {
                mma_bf16(oacc[nt], ah, bh[nt]);
                mma_bf16(oacc[nt], ah, bl[nt]);
                mma_bf16(oacc[nt], al, bh[nt]);
            }
        }
    }
    __syncthreads();

    // normalize + write split output
    const int r0 = wid * 16 + (lane >> 2);
    const float inv0 = 1.0f / dsum[r0];
    const float inv1 = 1.0f / dsum[r0 + 8];
    #pragma unroll
    for (int nt = 0; nt < 8; nt++) {
        int c = nt * 8 + 2 * (lane & 3);
        size_t i0 = (size_t)(b * NN + n0 + r0) * DD + h * HD + c;
        size_t i1 = (size_t)(b * NN + n0 + r0 + 8) * DD + h * HD + c;
        __nv_bfloat16 hh, ll;
        split2(oacc[nt][0] * inv0, hh, ll); g_ao_hi[i0]     = hh; g_ao_lo[i0]     = ll;
        split2(oacc[nt][1] * inv0, hh, ll); g_ao_hi[i0 + 1] = hh; g_ao_lo[i0 + 1] = ll;
        split2(oacc[nt][2] * inv1, hh, ll); g_ao_hi[i1]     = hh; g_ao_lo[i1]     = ll;
        split2(oacc[nt][3] * inv1, hh, ll); g_ao_hi[i1 + 1] = hh; g_ao_lo[i1 + 1] = ll;
    }
}

// ---------------------------------------------------------------------------
// attn.mean(): each softmax row sums to 1 -> mean == 1/KC exactly.
// ---------------------------------------------------------------------------
__global__ void finalize_mean(float* out, int out_size)
{
    const int base = BB * NN * DD;
    for (int i = base + threadIdx.x; i < out_size; i += blockDim.x)
        out[i] = 1.0f / (float)KC;
}

// ---------------------------------------------------------------------------
// Launch
// ---------------------------------------------------------------------------
extern "C" void kernel_launch(void* const* d_in, const int* in_sizes, int n_in,
                              void* d_out, int out_size)
{
    const float* x      = (const float*)d_in[0];
    const float* ctx    = (const float*)d_in[1];
    const float* q_w    = (const float*)d_in[2];
    const float* q_b    = (const float*)d_in[3];
    const float* kv_w   = (const float*)d_in[4];
    const float* kv_b   = (const float*)d_in[5];
    const float* proj_w = (const float*)d_in[6];
    const float* proj_b = (const float*)d_in[7];
    float* out = (float*)d_out;

    __nv_bfloat16 *xh, *xl, *qwh, *qwl, *kvwh, *kvwl, *pwh, *pwl;
    __nv_bfloat16 *cnh, *cnl, *qh, *ql, *kvh, *kvl, *aoh, *aol;
    cudaGetSymbolAddress((void**)&xh,  g_x_hi);  cudaGetSymbolAddress((void**)&xl,  g_x_lo);
    cudaGetSymbolAddress((void**)&qwh, g_qw_hi); cudaGetSymbolAddress((void**)&qwl, g_qw_lo);
    cudaGetSymbolAddress((void**)&kvwh,g_kvw_hi);cudaGetSymbolAddress((void**)&kvwl,g_kvw_lo);
    cudaGetSymbolAddress((void**)&pwh, g_pw_hi); cudaGetSymbolAddress((void**)&pwl, g_pw_lo);
    cudaGetSymbolAddress((void**)&cnh, g_cn_hi); cudaGetSymbolAddress((void**)&cnl, g_cn_lo);
    cudaGetSymbolAddress((void**)&qh,  g_q_hi);  cudaGetSymbolAddress((void**)&ql,  g_q_lo);
    cudaGetSymbolAddress((void**)&kvh, g_kv_hi); cudaGetSymbolAddress((void**)&kvl, g_kv_lo);
    cudaGetSymbolAddress((void**)&aoh, g_ao_hi); cudaGetSymbolAddress((void**)&aol, g_ao_lo);

    cudaFuncSetAttribute(mmgemm<true>,  cudaFuncAttributeMaxDynamicSharedMemorySize, GEMM_SMEM);
    cudaFuncSetAttribute(mmgemm<false>, cudaFuncAttributeMaxDynamicSharedMemorySize, GEMM_SMEM);
    cudaFuncSetAttribute(attn_mma,      cudaFuncAttributeMaxDynamicSharedMemorySize, ATTN_SMEM);

    // splits
    split_kernel<<<(BB*NN*DD/4 + 255)/256, 256>>>(x, xh, xl, BB*NN*DD);
    split_kernel<<<(DD*DD/4 + 255)/256, 256>>>(q_w, qwh, qwl, DD*DD);
    split_kernel<<<(DD*2*DD/4 + 255)/256, 256>>>(kv_w, kvwh, kvwl, DD*2*DD);
    split_kernel<<<(DD*DD/4 + 255)/256, 256>>>(proj_w, pwh, pwl, DD*DD);

    // rmsnorm
    rmsnorm_split<<<BB*KC, 256>>>(ctx);

    // q = (x @ q_w + q_b) * 0.125  -> split
    mmgemm<true><<<dim3(DD/GBN, BB*NN/GBM), 256, GEMM_SMEM>>>(
        xh, xl, qwh, qwl, q_b, 0.125f, nullptr, qh, ql, BB*NN, DD, DD);

    // kv = ctxn @ kv_w + kv_b  -> split
    mmgemm<true><<<dim3(2*DD/GBN, BB*KC/GBM), 256, GEMM_SMEM>>>(
        cnh, cnl, kvwh, kvwl, kv_b, 1.0f, nullptr, kvh, kvl, BB*KC, 2*DD, DD);

    // attention
    attn_mma<<<dim3(BB*HH, NN/ANT), 256, ATTN_SMEM>>>();

    // out = attn @ proj_w + proj_b (fp32)
    mmgemm<false><<<dim3(DD/GBN, BB*NN/GBM), 256, GEMM_SMEM>>>(
        aoh, aol, pwh, pwl, proj_b, 1.0f, out, nullptr, nullptr, BB*NN, DD, DD);

    if (out_size > BB * NN * DD)
        finalize_mean<<<1, 32>>>(out, out_size);
}